// round 5
// baseline (speedup 1.0000x reference)
#include <cuda_runtime.h>
#include <cuda_fp16.h>
#include <mma.h>
#include <cstdint>
#include <cstddef>

using namespace nvcuda;

// ---------------- problem constants ----------------
#define B_   64
#define T_   2048
#define C_   512
#define M_   80
#define P_   128
#define A_   128
#define H_   1024
#define FH_  4096         // 4*H
#define K1A  640          // P + C   (attention LSTM Wih cols)
#define KTA  1664         // P + C + H
#define K1D  1536         // H + C   (decoder  LSTM Wih cols)
#define KTD  2560         // H + C + H
#define NTILES 17         // 127-stride tiling of T=2048

#define LO_SCALE   1024.0f
#define LO_INV     0.0009765625f

// output offsets (float32 elements), tuple order:
// x_dec[64,1536], ctx[64,512], w_new[64,2048], ah, ac, dh, dc (each 64x1024)
#define O_XDEC 0
#define O_CTX  98304
#define O_WNEW 131072
#define O_AH   262144
#define O_AC   327680
#define O_DH   393216
#define O_DC   458752

// ---------------- device scratch (no allocation allowed) ----------------
__device__ __half g_x1_hi[B_ * KTA];
__device__ __half g_x1_lo[B_ * KTA];
__device__ __half g_x2_hi[B_ * KTD];
__device__ __half g_x2_lo[B_ * KTD];
__device__ __half g_wm_h[A_ * C_];           // att_Wm fp16 (keys path: fp16 is enough)
__device__ float  g_gates[B_ * FH_];         // reused for both LSTMs
__device__ float  g_ah[B_ * H_];             // zoneout-ed attention h (fp32)
__device__ float  g_s[B_ * A_];              // q + bq + bm
__device__ float  g_ctx_part[NTILES * B_ * C_];

// ---------------- helpers ----------------
__device__ __forceinline__ float sigm(float x) { return 1.f / (1.f + expf(-x)); }

__device__ __forceinline__ void split_hl(float v, __half& hi, __half& lo) {
    hi = __float2half_rn(v);
    lo = __float2half_rn((v - __half2float(hi)) * LO_SCALE);
}

__device__ __forceinline__ uint32_t rotl32(uint32_t x, int d) {
    return (x << d) | (x >> (32 - d));
}

// Threefry-2x32, 20 rounds (canonical; matches JAX's threefry2x32 primitive)
__device__ void tf2x32(uint32_t k0, uint32_t k1, uint32_t x0, uint32_t x1,
                       uint32_t& o0, uint32_t& o1) {
    uint32_t k2 = k0 ^ k1 ^ 0x1BD11BDAu;
    x0 += k0; x1 += k1;
    x0 += x1; x1 = rotl32(x1, 13); x1 ^= x0;
    x0 += x1; x1 = rotl32(x1, 15); x1 ^= x0;
    x0 += x1; x1 = rotl32(x1, 26); x1 ^= x0;
    x0 += x1; x1 = rotl32(x1,  6); x1 ^= x0;
    x0 += k1; x1 += k2 + 1u;
    x0 += x1; x1 = rotl32(x1, 17); x1 ^= x0;
    x0 += x1; x1 = rotl32(x1, 29); x1 ^= x0;
    x0 += x1; x1 = rotl32(x1, 16); x1 ^= x0;
    x0 += x1; x1 = rotl32(x1, 24); x1 ^= x0;
    x0 += k2; x1 += k0 + 2u;
    x0 += x1; x1 = rotl32(x1, 13); x1 ^= x0;
    x0 += x1; x1 = rotl32(x1, 15); x1 ^= x0;
    x0 += x1; x1 = rotl32(x1, 26); x1 ^= x0;
    x0 += x1; x1 = rotl32(x1,  6); x1 ^= x0;
    x0 += k0; x1 += k1 + 3u;
    x0 += x1; x1 = rotl32(x1, 17); x1 ^= x0;
    x0 += x1; x1 = rotl32(x1, 29); x1 ^= x0;
    x0 += x1; x1 = rotl32(x1, 16); x1 ^= x0;
    x0 += x1; x1 = rotl32(x1, 24); x1 ^= x0;
    x0 += k1; x1 += k2 + 4u;
    x0 += x1; x1 = rotl32(x1, 13); x1 ^= x0;
    x0 += x1; x1 = rotl32(x1, 15); x1 ^= x0;
    x0 += x1; x1 = rotl32(x1, 26); x1 ^= x0;
    x0 += x1; x1 = rotl32(x1,  6); x1 ^= x0;
    x0 += k2; x1 += k0 + 5u;
    o0 = x0; o1 = x1;
}

// jax_threefry_partitionable=True (default in modern JAX):
// split(key(42), 2):  dk_i = full 64-bit output of threefry(key, counter=(0, i))
__device__ __forceinline__ void derive_keys(uint32_t& a0, uint32_t& a1,
                                            uint32_t& b0, uint32_t& b1) {
    tf2x32(0u, 42u, 0u, 0u, a0, a1);   // dk1 = (o0, o1) @ counter 0
    tf2x32(0u, 42u, 0u, 1u, b0, b1);   // dk2 = (o0, o1) @ counter 1
}

// partitionable random_bits(32): element i -> counter (hi,lo)=(0,i), bits = o0 ^ o1
// bernoulli keep (p=0.5): uniform<0.5  <=>  top bit of bits == 0
__device__ __forceinline__ bool keep_mask(uint32_t k0, uint32_t k1, int i) {
    uint32_t o0, o1;
    tf2x32(k0, k1, 0u, (uint32_t)i, o0, o1);
    return ((o0 ^ o1) >> 31) == 0u;
}

// ================= K1: prenet + hi/lo staging =================
__global__ void prep_kernel(const float* __restrict__ x,
                            const float* __restrict__ ctx_att,
                            const float* __restrict__ h_att_h,
                            const float* __restrict__ h_dec_h,
                            const float* __restrict__ pre_W1, const float* __restrict__ pre_b1,
                            const float* __restrict__ pre_W2, const float* __restrict__ pre_b2,
                            const float* __restrict__ att_Wm) {
    int bid = blockIdx.x, tid = threadIdx.x;
    if (bid < 64) {
        __shared__ float sx[M_];
        __shared__ float sh1[P_];
        int b = bid;
        if (tid < M_) sx[tid] = x[b * M_ + tid];
        __syncthreads();
        uint32_t d10, d11, d20, d21;
        derive_keys(d10, d11, d20, d21);
        {   // layer 1 + dropout(dk1)
            int p = tid;
            float s = pre_b1[p];
            const float* wr = pre_W1 + p * M_;
            #pragma unroll
            for (int m = 0; m < M_; m++) s += wr[m] * sx[m];
            s = fmaxf(s, 0.f);
            s = keep_mask(d10, d11, b * P_ + p) ? s * 2.f : 0.f;
            sh1[p] = s;
        }
        __syncthreads();
        {   // layer 2 + dropout(dk2)
            int p = tid;
            float s = pre_b2[p];
            const float* wr = pre_W2 + p * P_;
            #pragma unroll 8
            for (int k = 0; k < P_; k++) s += wr[k] * sh1[k];
            s = fmaxf(s, 0.f);
            s = keep_mask(d20, d21, b * P_ + p) ? s * 2.f : 0.f;
            __half hi, lo; split_hl(s, hi, lo);
            g_x1_hi[b * KTA + p] = hi;
            g_x1_lo[b * KTA + p] = lo;
        }
    } else if (bid < 128) {
        int b = bid - 64;
        for (int j = tid; j < C_; j += 128) {
            __half hi, lo; split_hl(ctx_att[b * C_ + j], hi, lo);
            g_x1_hi[b * KTA + P_ + j] = hi;
            g_x1_lo[b * KTA + P_ + j] = lo;
        }
    } else if (bid < 192) {
        int b = bid - 128;
        for (int j = tid; j < H_; j += 128) {
            __half hi, lo; split_hl(h_att_h[b * H_ + j], hi, lo);
            g_x1_hi[b * KTA + K1A + j] = hi;
            g_x1_lo[b * KTA + K1A + j] = lo;
        }
    } else if (bid < 256) {
        int b = bid - 192;
        for (int j = tid; j < H_; j += 128) {
            __half hi, lo; split_hl(h_dec_h[b * H_ + j], hi, lo);
            g_x2_hi[b * KTD + K1D + j] = hi;
            g_x2_lo[b * KTD + K1D + j] = lo;
        }
    } else {
        int base = (bid - 256) * 512;
        for (int j = tid; j < 512; j += 128)
            g_wm_h[base + j] = __float2half(att_Wm[base + j]);
    }
}

// ================= K2/K7: LSTM gate GEMM (split-fp16 hi/lo wmma) =====
// G[64, 4096] = X[64, KTOT] @ [W1 | W2]^T    (W1: [4096,K1], W2: [4096,K2])
template<int KTOT, int K1, int K2>
__global__ void lstm_gemm(const __half* __restrict__ Xhi,
                          const __half* __restrict__ Xlo,
                          const float* __restrict__ W1,
                          const float* __restrict__ W2,
                          float* __restrict__ G) {
    __shared__ __half sXh[64 * 72];
    __shared__ __half sXl[64 * 72];
    __shared__ __half sWh[32 * 72];
    __shared__ __half sWl[32 * 72];
    int tid = threadIdx.x;
    int w = tid >> 5;
    int warp_m = w & 3;
    int warp_n = w >> 2;
    int n0 = blockIdx.x * 32;

    wmma::fragment<wmma::accumulator, 16, 16, 16, float> acc_h, acc_l;
    wmma::fill_fragment(acc_h, 0.f);
    wmma::fill_fragment(acc_l, 0.f);

    for (int c0 = 0; c0 < KTOT; c0 += 64) {
        #pragma unroll
        for (int rep = 0; rep < 2; rep++) {
            int lin = rep * 256 + tid;
            int row = lin >> 3, c8 = lin & 7;
            size_t off = (size_t)row * KTOT + c0 + c8 * 8;
            *(uint4*)(&sXh[row * 72 + c8 * 8]) = *(const uint4*)(Xhi + off);
            *(uint4*)(&sXl[row * 72 + c8 * 8]) = *(const uint4*)(Xlo + off);
        }
        const float* Wsrc; int ld;
        if (c0 < K1) { Wsrc = W1 + c0; ld = K1; }
        else         { Wsrc = W2 + (c0 - K1); ld = K2; }
        #pragma unroll
        for (int rep = 0; rep < 2; rep++) {
            int lin = rep * 256 + tid;
            int row = lin >> 4, c4 = lin & 15;
            float4 v = *(const float4*)(Wsrc + (size_t)(n0 + row) * ld + c4 * 4);
            __half hx, lx, hy, ly, hz, lz, hw, lw;
            split_hl(v.x, hx, lx); split_hl(v.y, hy, ly);
            split_hl(v.z, hz, lz); split_hl(v.w, hw, lw);
            int o = row * 72 + c4 * 4;
            sWh[o] = hx; sWh[o + 1] = hy; sWh[o + 2] = hz; sWh[o + 3] = hw;
            sWl[o] = lx; sWl[o + 1] = ly; sWl[o + 2] = lz; sWl[o + 3] = lw;
        }
        __syncthreads();
        #pragma unroll
        for (int kk = 0; kk < 4; kk++) {
            wmma::fragment<wmma::matrix_a, 16, 16, 16, __half, wmma::row_major> ah, al;
            wmma::fragment<wmma::matrix_b, 16, 16, 16, __half, wmma::col_major> bh, bl;
            wmma::load_matrix_sync(ah, sXh + warp_m * 16 * 72 + kk * 16, 72);
            wmma::load_matrix_sync(al, sXl + warp_m * 16 * 72 + kk * 16, 72);
            wmma::load_matrix_sync(bh, sWh + warp_n * 16 * 72 + kk * 16, 72);
            wmma::load_matrix_sync(bl, sWl + warp_n * 16 * 72 + kk * 16, 72);
            wmma::mma_sync(acc_h, ah, bh, acc_h);
            wmma::mma_sync(acc_l, al, bh, acc_l);
            wmma::mma_sync(acc_l, ah, bl, acc_l);
        }
        __syncthreads();
    }
    #pragma unroll
    for (int i = 0; i < acc_h.num_elements; i++)
        acc_h.x[i] += LO_INV * acc_l.x[i];
    wmma::store_matrix_sync(G + (size_t)(warp_m * 16) * FH_ + n0 + warp_n * 16,
                            acc_h, FH_, wmma::mem_row_major);
}

// ================= K3/K8: LSTM pointwise + zoneout =================
__global__ void lstm_point(const float* __restrict__ G,
                           const float* __restrict__ bih, const float* __restrict__ bhh,
                           const float* __restrict__ h_old, const float* __restrict__ c_old,
                           float* __restrict__ out_h, float* __restrict__ out_c,
                           float* __restrict__ gh_f32,        // nullable
                           __half* __restrict__ xh_dst,       // nullable (hi)
                           __half* __restrict__ xl_dst,       // nullable (lo)
                           int xh_stride, int xh_off,
                           float* __restrict__ xdec_dst) {    // nullable
    int e = blockIdx.x * blockDim.x + threadIdx.x;   // < 65536
    int b = e >> 10, a = e & 1023;
    const float* g = G + (size_t)b * FH_;
    float gi = g[a]        + bih[a]        + bhh[a];
    float gf = g[1024 + a] + bih[1024 + a] + bhh[1024 + a];
    float gg = g[2048 + a] + bih[2048 + a] + bhh[2048 + a];
    float go = g[3072 + a] + bih[3072 + a] + bhh[3072 + a];
    float c0 = c_old[e], h0 = h_old[e];
    float cn = sigm(gf) * c0 + sigm(gi) * tanhf(gg);
    float hn = sigm(go) * tanhf(cn);
    float hz = 0.9f * hn + 0.1f * h0;
    float cz = 0.9f * cn + 0.1f * c0;
    out_h[e] = hz; out_c[e] = cz;
    if (gh_f32)  gh_f32[e] = hz;
    if (xh_dst) {
        __half hi, lo; split_hl(hz, hi, lo);
        xh_dst[b * xh_stride + xh_off + a] = hi;
        xl_dst[b * xh_stride + xh_off + a] = lo;
    }
    if (xdec_dst) xdec_dst[b * 1536 + a] = hz;
}

// ================= K4: s = ah @ Wq^T + bq + bm =================
__global__ void q_kernel(const float* __restrict__ Wq, const float* __restrict__ bq,
                         const float* __restrict__ bm) {
    __shared__ float sAh[H_];
    int b = blockIdx.x, tid = threadIdx.x;     // 128 threads
    #pragma unroll
    for (int i = 0; i < 8; i++) sAh[i * 128 + tid] = g_ah[b * H_ + i * 128 + tid];
    __syncthreads();
    int a = tid;
    const float* wr = Wq + (size_t)a * H_;
    float s0 = 0.f, s1 = 0.f, s2 = 0.f, s3 = 0.f;
    #pragma unroll 4
    for (int h = 0; h < H_; h += 4) {
        s0 += wr[h]     * sAh[h];
        s1 += wr[h + 1] * sAh[h + 1];
        s2 += wr[h + 2] * sAh[h + 2];
        s3 += wr[h + 3] * sAh[h + 3];
    }
    g_s[b * A_ + a] = s0 + s1 + s2 + s3 + bq[a] + bm[a];
}

// ================= K5: fused attention (keys->e->p->w_new->ctx partial) ====
__global__ void att_kernel(const float* __restrict__ memory,
                           const float* __restrict__ w_att,
                           const float* __restrict__ att_v,
                           float* __restrict__ out_wnew) {
    extern __shared__ char sm[];
    __half* sMem  = (__half*)sm;                       // [128][136]
    __half* sWm   = (__half*)(sm + 128 * 136 * 2);     // [128][136]
    float*  sKeys = (float*)sm;                        // [128][132] aliases phase-1
    __shared__ float sP[128], sWn[128], sS[128], sV[128];

    int tid = threadIdx.x;
    int w = tid >> 5;
    int b = blockIdx.y;
    int t0 = 127 * blockIdx.x;

    if (tid < 128) { sS[tid] = g_s[b * A_ + tid]; sV[tid] = att_v[tid]; }

    wmma::fragment<wmma::accumulator, 16, 16, 16, float> acc[8];
    #pragma unroll
    for (int na = 0; na < 8; na++) wmma::fill_fragment(acc[na], 0.f);

    const float* memb = memory + (size_t)b * T_ * C_;

    // ---- phase 1: keys = mem_tile @ Wm^T (fp16 wmma, 4 K-chunks of 128) ----
    for (int cc = 0; cc < 4; cc++) {
        #pragma unroll
        for (int rep = 0; rep < 16; rep++) {
            int lin = rep * 256 + tid;
            int r = lin >> 5, c4 = lin & 31;
            int gr = t0 + r; if (gr > T_ - 1) gr = T_ - 1;
            float4 v = *(const float4*)(memb + (size_t)gr * C_ + cc * 128 + c4 * 4);
            __half2 h01 = __floats2half2_rn(v.x, v.y);
            __half2 h23 = __floats2half2_rn(v.z, v.w);
            *(__half2*)(&sMem[r * 136 + c4 * 4])     = h01;
            *(__half2*)(&sMem[r * 136 + c4 * 4 + 2]) = h23;
        }
        #pragma unroll
        for (int rep = 0; rep < 8; rep++) {
            int lin = rep * 256 + tid;
            int a = lin >> 4, c8 = lin & 15;
            uint4 v = *(const uint4*)(g_wm_h + a * C_ + cc * 128 + c8 * 8);
            *(uint4*)(&sWm[a * 136 + c8 * 8]) = v;
        }
        __syncthreads();
        #pragma unroll
        for (int kk = 0; kk < 8; kk++) {
            wmma::fragment<wmma::matrix_a, 16, 16, 16, __half, wmma::row_major> af;
            wmma::load_matrix_sync(af, sMem + w * 16 * 136 + kk * 16, 136);
            #pragma unroll
            for (int na = 0; na < 8; na++) {
                wmma::fragment<wmma::matrix_b, 16, 16, 16, __half, wmma::col_major> bf;
                wmma::load_matrix_sync(bf, sWm + na * 16 * 136 + kk * 16, 136);
                wmma::mma_sync(acc[na], af, bf, acc[na]);
            }
        }
        __syncthreads();
    }

    // ---- phase 2: e -> p -> w_new ----
    #pragma unroll
    for (int na = 0; na < 8; na++)
        wmma::store_matrix_sync(sKeys + (w * 16) * 132 + na * 16, acc[na], 132,
                                wmma::mem_row_major);
    __syncthreads();
    {
        int t = tid >> 1, half = tid & 1;
        float s = 0.f;
        const float* kr = sKeys + t * 132 + half * 64;
        const float* ss = sS + half * 64;
        const float* vv = sV + half * 64;
        #pragma unroll 8
        for (int j = 0; j < 64; j++) s += vv[j] * tanhf(kr[j] + ss[j]);
        s += __shfl_xor_sync(0xffffffffu, s, 1);
        if (half == 0) sP[t] = 1.f / (1.f + expf(-s));
    }
    __syncthreads();
    if (tid < 128) {
        int r = tid, t = t0 + r;
        float wn = 0.f; bool valid = false;
        if (t < T_) {
            if (r == 0) {
                if (blockIdx.x == 0) { wn = w_att[b * T_] * sP[0]; valid = true; }
            } else {
                wn = w_att[b * T_ + t] * sP[r]
                   + w_att[b * T_ + t - 1] * (1.f - sP[r - 1]);
                valid = true;
            }
        }
        sWn[r] = valid ? wn : 0.f;
        if (valid) out_wnew[b * T_ + t] = wn;
    }
    __syncthreads();

    // ---- phase 3: ctx partial = sum_t w_new[t] * memory[t, :] (fp32) ----
    {
        int c0 = tid * 2;
        float a0 = 0.f, a1 = 0.f;
        #pragma unroll 8
        for (int r = 0; r < 128; r++) {
            float wv = sWn[r];
            int gr = t0 + r; if (gr > T_ - 1) gr = T_ - 1;
            float2 m = *(const float2*)(memb + (size_t)gr * C_ + c0);
            a0 += wv * m.x; a1 += wv * m.y;
        }
        float* dst = g_ctx_part + ((size_t)blockIdx.x * B_ + b) * C_ + c0;
        dst[0] = a0; dst[1] = a1;
    }
}

// ================= K6: ctx reduce + staging =================
__global__ void ctx_reduce(float* __restrict__ out_ctx, float* __restrict__ out_xdec) {
    int e = blockIdx.x * blockDim.x + threadIdx.x;   // < 32768
    int b = e >> 9, c = e & 511;
    float s = 0.f;
    #pragma unroll
    for (int i = 0; i < NTILES; i++)
        s += g_ctx_part[((size_t)i * B_ + b) * C_ + c];
    out_ctx[e] = s;
    out_xdec[b * 1536 + 1024 + c] = s;
    __half hi, lo; split_hl(s, hi, lo);
    g_x2_hi[b * KTD + H_ + c] = hi;
    g_x2_lo[b * KTD + H_ + c] = lo;
}

// ================= launch =================
extern "C" void kernel_launch(void* const* d_in, const int* in_sizes, int n_in,
                              void* d_out, int out_size) {
    const float* x        = (const float*)d_in[0];
    const float* w_att    = (const float*)d_in[1];
    const float* ctx_att  = (const float*)d_in[2];
    const float* h_att_h  = (const float*)d_in[3];
    const float* h_att_c  = (const float*)d_in[4];
    const float* h_dec_h  = (const float*)d_in[5];
    const float* h_dec_c  = (const float*)d_in[6];
    const float* memory   = (const float*)d_in[7];
    const float* pre_W1   = (const float*)d_in[9];
    const float* pre_b1   = (const float*)d_in[10];
    const float* pre_W2   = (const float*)d_in[11];
    const float* pre_b2   = (const float*)d_in[12];
    const float* att_Wq   = (const float*)d_in[13];
    const float* att_bq   = (const float*)d_in[14];
    const float* att_Wm   = (const float*)d_in[15];
    const float* att_bm   = (const float*)d_in[16];
    const float* att_v    = (const float*)d_in[17];
    const float* arn_Wih  = (const float*)d_in[18];
    const float* arn_Whh  = (const float*)d_in[19];
    const float* arn_bih  = (const float*)d_in[20];
    const float* arn_bhh  = (const float*)d_in[21];
    const float* drn_Wih  = (const float*)d_in[22];
    const float* drn_Whh  = (const float*)d_in[23];
    const float* drn_bih  = (const float*)d_in[24];
    const float* drn_bhh  = (const float*)d_in[25];
    float* out = (float*)d_out;

    __half* x1h; cudaGetSymbolAddress((void**)&x1h, g_x1_hi);
    __half* x1l; cudaGetSymbolAddress((void**)&x1l, g_x1_lo);
    __half* x2h; cudaGetSymbolAddress((void**)&x2h, g_x2_hi);
    __half* x2l; cudaGetSymbolAddress((void**)&x2l, g_x2_lo);
    float*  gates; cudaGetSymbolAddress((void**)&gates, g_gates);
    float*  ahf;   cudaGetSymbolAddress((void**)&ahf, g_ah);

    cudaFuncSetAttribute(att_kernel, cudaFuncAttributeMaxDynamicSharedMemorySize, 69632);

    // K1: prenet + hi/lo staging + Wm convert
    prep_kernel<<<384, 128>>>(x, ctx_att, h_att_h, h_dec_h,
                              pre_W1, pre_b1, pre_W2, pre_b2, att_Wm);
    // K2: attention LSTM gates (split-fp16)
    lstm_gemm<KTA, K1A, H_><<<128, 256>>>(x1h, x1l, arn_Wih, arn_Whh, gates);
    // K3: attention LSTM pointwise -> ah, ac (+ stage ah into decoder input)
    lstm_point<<<256, 256>>>(gates, arn_bih, arn_bhh, h_att_h, h_att_c,
                             out + O_AH, out + O_AC, ahf, x2h, x2l, KTD, 0, nullptr);
    // K4: s = q + biases
    q_kernel<<<64, 128>>>(att_Wq, att_bq, att_bm);
    // K5: fused attention pass over memory
    att_kernel<<<dim3(NTILES, B_), 256, 69632>>>(memory, w_att, att_v, out + O_WNEW);
    // K6: ctx reduce + staging
    ctx_reduce<<<128, 256>>>(out + O_CTX, out + O_XDEC);
    // K7: decoder LSTM gates (split-fp16)
    lstm_gemm<KTD, K1D, H_><<<128, 256>>>(x2h, x2l, drn_Wih, drn_Whh, gates);
    // K8: decoder LSTM pointwise -> dh, dc (+ x_dec[:, :1024] = dh)
    lstm_point<<<256, 256>>>(gates, drn_bih, drn_bhh, h_dec_h, h_dec_c,
                             out + O_DH, out + O_DC, nullptr, nullptr, nullptr, 0, 0,
                             out + O_XDEC);
    (void)in_sizes; (void)n_in; (void)out_size;
}

// round 6
// speedup vs baseline: 1.4043x; 1.4043x over previous
#include <cuda_runtime.h>
#include <cuda_fp16.h>
#include <mma.h>
#include <cstdint>
#include <cstddef>

using namespace nvcuda;

// ---------------- problem constants ----------------
#define B_   64
#define T_   2048
#define C_   512
#define M_   80
#define P_   128
#define A_   128
#define H_   1024
#define FH_  4096         // 4*H
#define K1A  640          // P + C   (attention LSTM Wih cols)
#define KTA  1664         // P + C + H
#define K1D  1536         // H + C   (decoder  LSTM Wih cols)
#define KTD  2560         // H + C + H
#define NTILES 17         // 127-stride tiling of T=2048

#define LO_SCALE   1024.0f
#define LO_INV     0.0009765625f

// output offsets (float32 elements), tuple order:
// x_dec[64,1536], ctx[64,512], w_new[64,2048], ah, ac, dh, dc (each 64x1024)
#define O_XDEC 0
#define O_CTX  98304
#define O_WNEW 131072
#define O_AH   262144
#define O_AC   327680
#define O_DH   393216
#define O_DC   458752

// ---------------- device scratch (no allocation allowed) ----------------
__device__ __half g_x1_hi[B_ * KTA];
__device__ __half g_x1_lo[B_ * KTA];
__device__ __half g_x2_hi[B_ * KTD];
__device__ __half g_x2_lo[B_ * KTD];
__device__ __half g_wm_h[A_ * C_];           // att_Wm fp16 (keys path: fp16 is enough)
__device__ float  g_gates[B_ * FH_];         // reused for both LSTMs
__device__ float  g_ah[B_ * H_];             // zoneout-ed attention h (fp32)
__device__ float  g_s[B_ * A_];              // q + bq + bm
__device__ float  g_ctx_part[NTILES * B_ * C_];

// ---------------- helpers ----------------
__device__ __forceinline__ float sigm(float x) { return 1.f / (1.f + expf(-x)); }

__device__ __forceinline__ void split_hl(float v, __half& hi, __half& lo) {
    hi = __float2half_rn(v);
    lo = __float2half_rn((v - __half2float(hi)) * LO_SCALE);
}

__device__ __forceinline__ uint32_t rotl32(uint32_t x, int d) {
    return (x << d) | (x >> (32 - d));
}

// Threefry-2x32, 20 rounds (canonical; matches JAX's threefry2x32 primitive)
__device__ void tf2x32(uint32_t k0, uint32_t k1, uint32_t x0, uint32_t x1,
                       uint32_t& o0, uint32_t& o1) {
    uint32_t k2 = k0 ^ k1 ^ 0x1BD11BDAu;
    x0 += k0; x1 += k1;
    x0 += x1; x1 = rotl32(x1, 13); x1 ^= x0;
    x0 += x1; x1 = rotl32(x1, 15); x1 ^= x0;
    x0 += x1; x1 = rotl32(x1, 26); x1 ^= x0;
    x0 += x1; x1 = rotl32(x1,  6); x1 ^= x0;
    x0 += k1; x1 += k2 + 1u;
    x0 += x1; x1 = rotl32(x1, 17); x1 ^= x0;
    x0 += x1; x1 = rotl32(x1, 29); x1 ^= x0;
    x0 += x1; x1 = rotl32(x1, 16); x1 ^= x0;
    x0 += x1; x1 = rotl32(x1, 24); x1 ^= x0;
    x0 += k2; x1 += k0 + 2u;
    x0 += x1; x1 = rotl32(x1, 13); x1 ^= x0;
    x0 += x1; x1 = rotl32(x1, 15); x1 ^= x0;
    x0 += x1; x1 = rotl32(x1, 26); x1 ^= x0;
    x0 += x1; x1 = rotl32(x1,  6); x1 ^= x0;
    x0 += k0; x1 += k1 + 3u;
    x0 += x1; x1 = rotl32(x1, 17); x1 ^= x0;
    x0 += x1; x1 = rotl32(x1, 29); x1 ^= x0;
    x0 += x1; x1 = rotl32(x1, 16); x1 ^= x0;
    x0 += x1; x1 = rotl32(x1, 24); x1 ^= x0;
    x0 += k1; x1 += k2 + 4u;
    x0 += x1; x1 = rotl32(x1, 13); x1 ^= x0;
    x0 += x1; x1 = rotl32(x1, 15); x1 ^= x0;
    x0 += x1; x1 = rotl32(x1, 26); x1 ^= x0;
    x0 += x1; x1 = rotl32(x1,  6); x1 ^= x0;
    x0 += k2; x1 += k0 + 5u;
    o0 = x0; o1 = x1;
}

// jax_threefry_partitionable=True (modern JAX default):
// split(key(42), 2):  dk_i = full 64-bit output of threefry(key, counter=(0, i))
__device__ __forceinline__ void derive_keys(uint32_t& a0, uint32_t& a1,
                                            uint32_t& b0, uint32_t& b1) {
    tf2x32(0u, 42u, 0u, 0u, a0, a1);   // dk1
    tf2x32(0u, 42u, 0u, 1u, b0, b1);   // dk2
}

// partitionable random_bits(32): element i -> counter (0, i), bits = o0 ^ o1
__device__ __forceinline__ bool keep_mask(uint32_t k0, uint32_t k1, int i) {
    uint32_t o0, o1;
    tf2x32(k0, k1, 0u, (uint32_t)i, o0, o1);
    return ((o0 ^ o1) >> 31) == 0u;
}

// ================= K1: prenet + hi/lo staging =================
__global__ void prep_kernel(const float* __restrict__ x,
                            const float* __restrict__ ctx_att,
                            const float* __restrict__ h_att_h,
                            const float* __restrict__ h_dec_h,
                            const float* __restrict__ pre_W1, const float* __restrict__ pre_b1,
                            const float* __restrict__ pre_W2, const float* __restrict__ pre_b2,
                            const float* __restrict__ att_Wm) {
    int bid = blockIdx.x, tid = threadIdx.x;
    if (bid < 64) {
        __shared__ float sx[M_];
        __shared__ float sh1[P_];
        int b = bid;
        if (tid < M_) sx[tid] = x[b * M_ + tid];
        __syncthreads();
        uint32_t d10, d11, d20, d21;
        derive_keys(d10, d11, d20, d21);
        {   // layer 1 + dropout(dk1)
            int p = tid;
            float s = pre_b1[p];
            const float* wr = pre_W1 + p * M_;
            #pragma unroll
            for (int m = 0; m < M_; m++) s += wr[m] * sx[m];
            s = fmaxf(s, 0.f);
            s = keep_mask(d10, d11, b * P_ + p) ? s * 2.f : 0.f;
            sh1[p] = s;
        }
        __syncthreads();
        {   // layer 2 + dropout(dk2)
            int p = tid;
            float s = pre_b2[p];
            const float* wr = pre_W2 + p * P_;
            #pragma unroll 8
            for (int k = 0; k < P_; k++) s += wr[k] * sh1[k];
            s = fmaxf(s, 0.f);
            s = keep_mask(d20, d21, b * P_ + p) ? s * 2.f : 0.f;
            __half hi, lo; split_hl(s, hi, lo);
            g_x1_hi[b * KTA + p] = hi;
            g_x1_lo[b * KTA + p] = lo;
        }
    } else if (bid < 128) {
        int b = bid - 64;
        for (int j = tid; j < C_; j += 128) {
            __half hi, lo; split_hl(ctx_att[b * C_ + j], hi, lo);
            g_x1_hi[b * KTA + P_ + j] = hi;
            g_x1_lo[b * KTA + P_ + j] = lo;
        }
    } else if (bid < 192) {
        int b = bid - 128;
        for (int j = tid; j < H_; j += 128) {
            __half hi, lo; split_hl(h_att_h[b * H_ + j], hi, lo);
            g_x1_hi[b * KTA + K1A + j] = hi;
            g_x1_lo[b * KTA + K1A + j] = lo;
        }
    } else if (bid < 256) {
        int b = bid - 192;
        for (int j = tid; j < H_; j += 128) {
            __half hi, lo; split_hl(h_dec_h[b * H_ + j], hi, lo);
            g_x2_hi[b * KTD + K1D + j] = hi;
            g_x2_lo[b * KTD + K1D + j] = lo;
        }
    } else {
        int base = (bid - 256) * 512;
        for (int j = tid; j < 512; j += 128)
            g_wm_h[base + j] = __float2half(att_Wm[base + j]);
    }
}

// ================= K2/K7: LSTM gate GEMM (split-fp16 hi/lo wmma, prefetch) ==
// G[64, 4096] = X[64, KTOT] @ [W1 | W2]^T    (W1: [4096,K1], W2: [4096,K2])
template<int KTOT, int K1, int K2>
__global__ void lstm_gemm(const __half* __restrict__ Xhi,
                          const __half* __restrict__ Xlo,
                          const float* __restrict__ W1,
                          const float* __restrict__ W2,
                          float* __restrict__ G) {
    __shared__ __half sXh[64 * 72];
    __shared__ __half sXl[64 * 72];
    __shared__ __half sWh[32 * 72];
    __shared__ __half sWl[32 * 72];
    int tid = threadIdx.x;
    int w = tid >> 5;
    int warp_m = w & 3;
    int warp_n = w >> 2;
    int n0 = blockIdx.x * 32;

    // per-thread load coordinates
    int xrow0 = tid >> 3,            xc8 = tid & 7;        // X: rows tid/8, 8 halves
    int xrow1 = (256 + tid) >> 3;                          //   second rep
    int wrow0 = tid >> 4,            wc4 = tid & 15;       // W: rows tid/16, 4 floats
    int wrow1 = (256 + tid) >> 4;

    wmma::fragment<wmma::accumulator, 16, 16, 16, float> acc_h, acc_l;
    wmma::fill_fragment(acc_h, 0.f);
    wmma::fill_fragment(acc_l, 0.f);

    uint4  rXh0, rXh1, rXl0, rXl1;
    float4 rW0, rW1;

    auto fetch = [&](int c0) {
        size_t o0 = (size_t)xrow0 * KTOT + c0 + xc8 * 8;
        size_t o1 = (size_t)xrow1 * KTOT + c0 + xc8 * 8;
        rXh0 = *(const uint4*)(Xhi + o0);
        rXh1 = *(const uint4*)(Xhi + o1);
        rXl0 = *(const uint4*)(Xlo + o0);
        rXl1 = *(const uint4*)(Xlo + o1);
        const float* Wsrc; int ld;
        if (c0 < K1) { Wsrc = W1 + c0; ld = K1; }
        else         { Wsrc = W2 + (c0 - K1); ld = K2; }
        rW0 = *(const float4*)(Wsrc + (size_t)(n0 + wrow0) * ld + wc4 * 4);
        rW1 = *(const float4*)(Wsrc + (size_t)(n0 + wrow1) * ld + wc4 * 4);
    };

    auto commit = [&]() {
        *(uint4*)(&sXh[xrow0 * 72 + xc8 * 8]) = rXh0;
        *(uint4*)(&sXh[xrow1 * 72 + xc8 * 8]) = rXh1;
        *(uint4*)(&sXl[xrow0 * 72 + xc8 * 8]) = rXl0;
        *(uint4*)(&sXl[xrow1 * 72 + xc8 * 8]) = rXl1;
        __half h0, l0, h1, l1, h2, l2, h3, l3;
        int o = wrow0 * 72 + wc4 * 4;
        split_hl(rW0.x, h0, l0); split_hl(rW0.y, h1, l1);
        split_hl(rW0.z, h2, l2); split_hl(rW0.w, h3, l3);
        sWh[o] = h0; sWh[o+1] = h1; sWh[o+2] = h2; sWh[o+3] = h3;
        sWl[o] = l0; sWl[o+1] = l1; sWl[o+2] = l2; sWl[o+3] = l3;
        o = wrow1 * 72 + wc4 * 4;
        split_hl(rW1.x, h0, l0); split_hl(rW1.y, h1, l1);
        split_hl(rW1.z, h2, l2); split_hl(rW1.w, h3, l3);
        sWh[o] = h0; sWh[o+1] = h1; sWh[o+2] = h2; sWh[o+3] = h3;
        sWl[o] = l0; sWl[o+1] = l1; sWl[o+2] = l2; sWl[o+3] = l3;
    };

    fetch(0);
    for (int c0 = 0; c0 < KTOT; c0 += 64) {
        __syncthreads();           // previous MMA done reading smem
        commit();
        __syncthreads();
        if (c0 + 64 < KTOT) fetch(c0 + 64);   // overlap next loads with MMA
        #pragma unroll
        for (int kk = 0; kk < 4; kk++) {
            wmma::fragment<wmma::matrix_a, 16, 16, 16, __half, wmma::row_major> ah, al;
            wmma::fragment<wmma::matrix_b, 16, 16, 16, __half, wmma::col_major> bh, bl;
            wmma::load_matrix_sync(ah, sXh + warp_m * 16 * 72 + kk * 16, 72);
            wmma::load_matrix_sync(al, sXl + warp_m * 16 * 72 + kk * 16, 72);
            wmma::load_matrix_sync(bh, sWh + warp_n * 16 * 72 + kk * 16, 72);
            wmma::load_matrix_sync(bl, sWl + warp_n * 16 * 72 + kk * 16, 72);
            wmma::mma_sync(acc_h, ah, bh, acc_h);
            wmma::mma_sync(acc_l, al, bh, acc_l);
            wmma::mma_sync(acc_l, ah, bl, acc_l);
        }
    }
    #pragma unroll
    for (int i = 0; i < acc_h.num_elements; i++)
        acc_h.x[i] += LO_INV * acc_l.x[i];
    wmma::store_matrix_sync(G + (size_t)(warp_m * 16) * FH_ + n0 + warp_n * 16,
                            acc_h, FH_, wmma::mem_row_major);
}

// ================= K3/K8: LSTM pointwise + zoneout =================
__global__ void lstm_point(const float* __restrict__ G,
                           const float* __restrict__ bih, const float* __restrict__ bhh,
                           const float* __restrict__ h_old, const float* __restrict__ c_old,
                           float* __restrict__ out_h, float* __restrict__ out_c,
                           float* __restrict__ gh_f32,        // nullable
                           __half* __restrict__ xh_dst,       // nullable (hi)
                           __half* __restrict__ xl_dst,       // nullable (lo)
                           int xh_stride, int xh_off,
                           float* __restrict__ xdec_dst) {    // nullable
    int e = blockIdx.x * blockDim.x + threadIdx.x;   // < 65536
    int b = e >> 10, a = e & 1023;
    const float* g = G + (size_t)b * FH_;
    float gi = g[a]        + bih[a]        + bhh[a];
    float gf = g[1024 + a] + bih[1024 + a] + bhh[1024 + a];
    float gg = g[2048 + a] + bih[2048 + a] + bhh[2048 + a];
    float go = g[3072 + a] + bih[3072 + a] + bhh[3072 + a];
    float c0 = c_old[e], h0 = h_old[e];
    float cn = sigm(gf) * c0 + sigm(gi) * tanhf(gg);
    float hn = sigm(go) * tanhf(cn);
    float hz = 0.9f * hn + 0.1f * h0;
    float cz = 0.9f * cn + 0.1f * c0;
    out_h[e] = hz; out_c[e] = cz;
    if (gh_f32)  gh_f32[e] = hz;
    if (xh_dst) {
        __half hi, lo; split_hl(hz, hi, lo);
        xh_dst[b * xh_stride + xh_off + a] = hi;
        xl_dst[b * xh_stride + xh_off + a] = lo;
    }
    if (xdec_dst) xdec_dst[b * 1536 + a] = hz;
}

// ================= K4: s = ah @ Wq^T + bq + bm  (warp per output) ==========
__global__ void q_kernel(const float* __restrict__ Wq, const float* __restrict__ bq,
                         const float* __restrict__ bm) {
    int gw = (blockIdx.x * blockDim.x + threadIdx.x) >> 5;   // 0..8191
    int lane = threadIdx.x & 31;
    int b = gw >> 7, a = gw & 127;
    const float4* wr = (const float4*)(Wq + (size_t)a * H_);
    const float4* hr = (const float4*)(g_ah + (size_t)b * H_);
    float s = 0.f;
    #pragma unroll
    for (int i = 0; i < 8; i++) {
        float4 wv = wr[i * 32 + lane];       // coalesced 128B per warp
        float4 hv = hr[i * 32 + lane];
        s += wv.x * hv.x + wv.y * hv.y + wv.z * hv.z + wv.w * hv.w;
    }
    #pragma unroll
    for (int off = 16; off; off >>= 1) s += __shfl_xor_sync(0xffffffffu, s, off);
    if (lane == 0) g_s[b * A_ + a] = s + bq[a] + bm[a];
}

// ================= K5: fused attention (keys->e->p->w_new->ctx partial) ====
__global__ void att_kernel(const float* __restrict__ memory,
                           const float* __restrict__ w_att,
                           const float* __restrict__ att_v,
                           float* __restrict__ out_wnew) {
    extern __shared__ char sm[];
    __half* sMem  = (__half*)sm;                       // [128][136]
    __half* sWm   = (__half*)(sm + 128 * 136 * 2);     // [128][136]
    float*  sKeys = (float*)sm;                        // [128][132] aliases phase-1
    __shared__ float sP[128], sWn[128], sS[128], sV[128];

    int tid = threadIdx.x;
    int w = tid >> 5;
    int b = blockIdx.y;
    int t0 = 127 * blockIdx.x;

    if (tid < 128) { sS[tid] = g_s[b * A_ + tid]; sV[tid] = att_v[tid]; }

    wmma::fragment<wmma::accumulator, 16, 16, 16, float> acc[8];
    #pragma unroll
    for (int na = 0; na < 8; na++) wmma::fill_fragment(acc[na], 0.f);

    const float* memb = memory + (size_t)b * T_ * C_;

    // ---- phase 1: keys = mem_tile @ Wm^T (fp16 wmma, 4 K-chunks of 128) ----
    for (int cc = 0; cc < 4; cc++) {
        #pragma unroll
        for (int rep = 0; rep < 16; rep++) {
            int lin = rep * 256 + tid;
            int r = lin >> 5, c4 = lin & 31;
            int gr = t0 + r; if (gr > T_ - 1) gr = T_ - 1;
            float4 v = *(const float4*)(memb + (size_t)gr * C_ + cc * 128 + c4 * 4);
            __half2 h01 = __floats2half2_rn(v.x, v.y);
            __half2 h23 = __floats2half2_rn(v.z, v.w);
            *(__half2*)(&sMem[r * 136 + c4 * 4])     = h01;
            *(__half2*)(&sMem[r * 136 + c4 * 4 + 2]) = h23;
        }
        #pragma unroll
        for (int rep = 0; rep < 8; rep++) {
            int lin = rep * 256 + tid;
            int a = lin >> 4, c8 = lin & 15;
            uint4 v = *(const uint4*)(g_wm_h + a * C_ + cc * 128 + c8 * 8);
            *(uint4*)(&sWm[a * 136 + c8 * 8]) = v;
        }
        __syncthreads();
        #pragma unroll
        for (int kk = 0; kk < 8; kk++) {
            wmma::fragment<wmma::matrix_a, 16, 16, 16, __half, wmma::row_major> af;
            wmma::load_matrix_sync(af, sMem + w * 16 * 136 + kk * 16, 136);
            #pragma unroll
            for (int na = 0; na < 8; na++) {
                wmma::fragment<wmma::matrix_b, 16, 16, 16, __half, wmma::col_major> bf;
                wmma::load_matrix_sync(bf, sWm + na * 16 * 136 + kk * 16, 136);
                wmma::mma_sync(acc[na], af, bf, acc[na]);
            }
        }
        __syncthreads();
    }

    // ---- phase 2: e -> p -> w_new ----
    #pragma unroll
    for (int na = 0; na < 8; na++)
        wmma::store_matrix_sync(sKeys + (w * 16) * 132 + na * 16, acc[na], 132,
                                wmma::mem_row_major);
    __syncthreads();
    {
        int t = tid >> 1, half = tid & 1;
        float s = 0.f;
        const float* kr = sKeys + t * 132 + half * 64;
        const float* ss = sS + half * 64;
        const float* vv = sV + half * 64;
        #pragma unroll 8
        for (int j = 0; j < 64; j++) s += vv[j] * tanhf(kr[j] + ss[j]);
        s += __shfl_xor_sync(0xffffffffu, s, 1);
        if (half == 0) sP[t] = 1.f / (1.f + expf(-s));
    }
    __syncthreads();
    if (tid < 128) {
        int r = tid, t = t0 + r;
        float wn = 0.f; bool valid = false;
        if (t < T_) {
            if (r == 0) {
                if (blockIdx.x == 0) { wn = w_att[b * T_] * sP[0]; valid = true; }
            } else {
                wn = w_att[b * T_ + t] * sP[r]
                   + w_att[b * T_ + t - 1] * (1.f - sP[r - 1]);
                valid = true;
            }
        }
        sWn[r] = valid ? wn : 0.f;
        if (valid) out_wnew[b * T_ + t] = wn;
    }
    __syncthreads();

    // ---- phase 3: ctx partial = sum_t w_new[t] * memory[t, :] (fp32) ----
    {
        int c0 = tid * 2;
        float a0 = 0.f, a1 = 0.f;
        #pragma unroll 8
        for (int r = 0; r < 128; r++) {
            float wv = sWn[r];
            int gr = t0 + r; if (gr > T_ - 1) gr = T_ - 1;
            float2 m = *(const float2*)(memb + (size_t)gr * C_ + c0);
            a0 += wv * m.x; a1 += wv * m.y;
        }
        float* dst = g_ctx_part + ((size_t)blockIdx.x * B_ + b) * C_ + c0;
        dst[0] = a0; dst[1] = a1;
    }
}

// ================= K6: ctx reduce + staging =================
__global__ void ctx_reduce(float* __restrict__ out_ctx, float* __restrict__ out_xdec) {
    int e = blockIdx.x * blockDim.x + threadIdx.x;   // < 32768
    int b = e >> 9, c = e & 511;
    float s = 0.f;
    #pragma unroll
    for (int i = 0; i < NTILES; i++)
        s += g_ctx_part[((size_t)i * B_ + b) * C_ + c];
    out_ctx[e] = s;
    out_xdec[b * 1536 + 1024 + c] = s;
    __half hi, lo; split_hl(s, hi, lo);
    g_x2_hi[b * KTD + H_ + c] = hi;
    g_x2_lo[b * KTD + H_ + c] = lo;
}

// ================= launch =================
extern "C" void kernel_launch(void* const* d_in, const int* in_sizes, int n_in,
                              void* d_out, int out_size) {
    const float* x        = (const float*)d_in[0];
    const float* w_att    = (const float*)d_in[1];
    const float* ctx_att  = (const float*)d_in[2];
    const float* h_att_h  = (const float*)d_in[3];
    const float* h_att_c  = (const float*)d_in[4];
    const float* h_dec_h  = (const float*)d_in[5];
    const float* h_dec_c  = (const float*)d_in[6];
    const float* memory   = (const float*)d_in[7];
    const float* pre_W1   = (const float*)d_in[9];
    const float* pre_b1   = (const float*)d_in[10];
    const float* pre_W2   = (const float*)d_in[11];
    const float* pre_b2   = (const float*)d_in[12];
    const float* att_Wq   = (const float*)d_in[13];
    const float* att_bq   = (const float*)d_in[14];
    const float* att_Wm   = (const float*)d_in[15];
    const float* att_bm   = (const float*)d_in[16];
    const float* att_v    = (const float*)d_in[17];
    const float* arn_Wih  = (const float*)d_in[18];
    const float* arn_Whh  = (const float*)d_in[19];
    const float* arn_bih  = (const float*)d_in[20];
    const float* arn_bhh  = (const float*)d_in[21];
    const float* drn_Wih  = (const float*)d_in[22];
    const float* drn_Whh  = (const float*)d_in[23];
    const float* drn_bih  = (const float*)d_in[24];
    const float* drn_bhh  = (const float*)d_in[25];
    float* out = (float*)d_out;

    __half* x1h; cudaGetSymbolAddress((void**)&x1h, g_x1_hi);
    __half* x1l; cudaGetSymbolAddress((void**)&x1l, g_x1_lo);
    __half* x2h; cudaGetSymbolAddress((void**)&x2h, g_x2_hi);
    __half* x2l; cudaGetSymbolAddress((void**)&x2l, g_x2_lo);
    float*  gates; cudaGetSymbolAddress((void**)&gates, g_gates);
    float*  ahf;   cudaGetSymbolAddress((void**)&ahf, g_ah);

    cudaFuncSetAttribute(att_kernel, cudaFuncAttributeMaxDynamicSharedMemorySize, 69632);

    // K1: prenet + hi/lo staging + Wm convert
    prep_kernel<<<384, 128>>>(x, ctx_att, h_att_h, h_dec_h,
                              pre_W1, pre_b1, pre_W2, pre_b2, att_Wm);
    // K2: attention LSTM gates (split-fp16, prefetch)
    lstm_gemm<KTA, K1A, H_><<<128, 256>>>(x1h, x1l, arn_Wih, arn_Whh, gates);
    // K3: attention LSTM pointwise -> ah, ac (+ stage ah into decoder input)
    lstm_point<<<256, 256>>>(gates, arn_bih, arn_bhh, h_att_h, h_att_c,
                             out + O_AH, out + O_AC, ahf, x2h, x2l, KTD, 0, nullptr);
    // K4: s = q + biases (warp-per-output, coalesced)
    q_kernel<<<1024, 256>>>(att_Wq, att_bq, att_bm);
    // K5: fused attention pass over memory
    att_kernel<<<dim3(NTILES, B_), 256, 69632>>>(memory, w_att, att_v, out + O_WNEW);
    // K6: ctx reduce + staging
    ctx_reduce<<<128, 256>>>(out + O_CTX, out + O_XDEC);
    // K7: decoder LSTM gates (split-fp16, prefetch)
    lstm_gemm<KTD, K1D, H_><<<128, 256>>>(x2h, x2l, drn_Wih, drn_Whh, gates);
    // K8: decoder LSTM pointwise -> dh, dc (+ x_dec[:, :1024] = dh)
    lstm_point<<<256, 256>>>(gates, drn_bih, drn_bhh, h_dec_h, h_dec_c,
                             out + O_DH, out + O_DC, nullptr, nullptr, nullptr, 0, 0,
                             out + O_XDEC);
    (void)in_sizes; (void)n_in; (void)out_size;
}